// round 13
// baseline (speedup 1.0000x reference)
#include <cuda_runtime.h>

// Problem constants
#define B_   32
#define L_   1024
#define K_   64
#define N_   8
#define BLK_ (B_*L_*K_)          // 2,097,152 samples
#define CHUNK_L 32
#define CHUNKS  (L_/CHUNK_L)
#define NPART   (B_*CHUNKS)

// Output layout (flat f32, reference tuple order)
#define OFF_VQ  0L
#define OFF_HQ  4194304L
#define OFF_EBD 37748736L
#define OFF_EBC 39845888L
#define OFF_WD  41943040L
#define OFF_WC  48234496L

#define RND_MAGIC 12582912.0f    // 1.5 * 2^23 : exact RNE round for |x| <= 8

// Constant table layout (floats)
#define T_W1 0        // 160
#define T_W2 160      // 1024
#define T_B1 1184     // 32
#define T_B2 1216     // 32
#define T_WH 1248     // 256 (per i: d0 d1 d2 c0 c1 c2 0 0)
#define T_BS 1504     // 16  ([0..5]=bd,bc  [8..15]=s2d s4d s2c s4c r2d r4d r2c r4c)
#define T_TOTAL 1520

typedef unsigned long long ull;

// Scratch (device globals: allocation-free)
__device__ float    g_part[NPART*K_];
__device__ float    g_avg[B_*K_];
__device__ unsigned g_ctr;
__device__ __align__(16) float g_stage[T_TOTAL];

// One constant table (uniform-constant port, not L1)
__constant__ __align__(16) float cT[T_TOTAL];

// ---- packed f32x2 helpers (bitwise-exact dual fp32 ops) ----
__device__ __forceinline__ ull pack2(float x, float y) {
    ull r; asm("mov.b64 %0,{%1,%2};" : "=l"(r) : "f"(x), "f"(y)); return r;
}
__device__ __forceinline__ void unpack2(ull v, float& x, float& y) {
    asm("mov.b64 {%0,%1},%2;" : "=f"(x), "=f"(y) : "l"(v));
}
__device__ __forceinline__ ull ffma2(ull a, ull b, ull c) {
    ull d; asm("fma.rn.f32x2 %0,%1,%2,%3;" : "=l"(d) : "l"(a), "l"(b), "l"(c)); return d;
}

// ---------------------------------------------------------------------------
// Kernel P: stage constant table (runs on forked stream, parallel with kA)
// ---------------------------------------------------------------------------
__global__ __launch_bounds__(256) void kP_prep(
    const float* __restrict__ W1, const float* __restrict__ b1,
    const float* __restrict__ W2, const float* __restrict__ b2,
    const float* __restrict__ Wd, const float* __restrict__ Wc,
    const float* __restrict__ bd, const float* __restrict__ bc,
    const float* __restrict__ s2d, const float* __restrict__ s4d,
    const float* __restrict__ s2c, const float* __restrict__ s4c)
{
    const int tid = threadIdx.x;
    for (int i = tid; i < 160;  i += 256) g_stage[T_W1 + i] = W1[i];
    for (int i = tid; i < 1024; i += 256) g_stage[T_W2 + i] = W2[i];
    if (tid < 32) {
        g_stage[T_B1 + tid] = b1[tid];
        g_stage[T_B2 + tid] = b2[tid];
        g_stage[T_WH + tid*8+0] = Wd[tid*3+0];
        g_stage[T_WH + tid*8+1] = Wd[tid*3+1];
        g_stage[T_WH + tid*8+2] = Wd[tid*3+2];
        g_stage[T_WH + tid*8+3] = Wc[tid*3+0];
        g_stage[T_WH + tid*8+4] = Wc[tid*3+1];
        g_stage[T_WH + tid*8+5] = Wc[tid*3+2];
        g_stage[T_WH + tid*8+6] = 0.0f;
        g_stage[T_WH + tid*8+7] = 0.0f;
    }
    if (tid == 0) {
        g_stage[T_BS+0] = bd[0]; g_stage[T_BS+1] = bd[1]; g_stage[T_BS+2] = bd[2];
        g_stage[T_BS+3] = bc[0]; g_stage[T_BS+4] = bc[1]; g_stage[T_BS+5] = bc[2];
        g_stage[T_BS+6] = 0.0f;  g_stage[T_BS+7] = 0.0f;
        float a = *s2d, bq = *s4d, c = *s2c, d = *s4c;
        g_stage[T_BS+8]  = a;      g_stage[T_BS+9]  = bq;
        g_stage[T_BS+10] = c;      g_stage[T_BS+11] = d;
        g_stage[T_BS+12] = 1.0f/a; g_stage[T_BS+13] = 1.0f/bq;
        g_stage[T_BS+14] = 1.0f/c; g_stage[T_BS+15] = 1.0f/d;
    }
}

// ---------------------------------------------------------------------------
// Kernel A: pure avg_power via float4 loads (R11 reduction, bit-identical
// order: same l-partition, same fmaf chain, same (P0+P1)+(P2+P3) tree).
// ---------------------------------------------------------------------------
__global__ __launch_bounds__(128) void kA_avg(const float* __restrict__ H)
{
    const int bx  = blockIdx.x;
    const int tid = threadIdx.x;

    const int b     = bx >> 5;
    const int chunk = bx & 31;
    const int k2    = tid & 31;
    const int lsub  = tid >> 5;

    const float4* __restrict__ H4 = (const float4*)H;

    float pA = 0.0f, pB = 0.0f;
#pragma unroll
    for (int r = 0; r < CHUNK_L/4; ++r) {
        const int l  = chunk*CHUNK_L + r*4 + lsub;
        const long bl = (long)b*L_ + l;
        float hpA = 0.0f, hpB = 0.0f;
#pragma unroll
        for (int n = 0; n < N_; ++n) {
            float4 hv = H4[(bl*N_ + n)*(K_/2) + k2];
            hpA = fmaf(hv.x, hv.x, fmaf(hv.y, hv.y, hpA));
            hpB = fmaf(hv.z, hv.z, fmaf(hv.w, hv.w, hpB));
        }
        pA += hpA;
        pB += hpB;
    }

    __shared__ float2 sm[128];
    __shared__ unsigned s_ticket;
    sm[tid] = make_float2(pA, pB);
    __syncthreads();
    if (tid < 32) {
        float2 q0 = sm[tid], q1 = sm[tid+32], q2 = sm[tid+64], q3 = sm[tid+96];
        float sA = (q0.x + q1.x) + (q2.x + q3.x);
        float sB = (q0.y + q1.y) + (q2.y + q3.y);
        g_part[bx*64 + 2*tid + 0] = sA;
        g_part[bx*64 + 2*tid + 1] = sB;
    }
    __threadfence();
    __syncthreads();
    if (tid == 0) s_ticket = atomicAdd(&g_ctr, 1u);
    __syncthreads();

    if (s_ticket == NPART - 1) {
        for (int i = tid; i < B_*K_; i += 128) {
            const int bb = i >> 6;
            const int kk = i & 63;
            float s = 0.0f;
#pragma unroll
            for (int c = 0; c < CHUNKS; ++c)
                s += g_part[(bb*CHUNKS + c)*64 + kk];
            g_avg[i] = s * (1.0f/1024.0f);
        }
        if (tid == 0) g_ctr = 0;
    }
}

// ---------------------------------------------------------------------------
// lsq forward (scalar): round(clip(x*rs, Qn, Qp)) * s, exact RNE via magic.
// ---------------------------------------------------------------------------
__device__ __forceinline__ float lsqv(float x, float rs, float s, float qn, float qp) {
    float t = x * rs;
    t = fminf(fmaxf(t, qn), qp);
    t = __fadd_rn(__fadd_rn(t, RND_MAGIC), -RND_MAGIC);
    return t * s;
}

// ---------------------------------------------------------------------------
// Kernel C: R11 configuration verbatim (best measured: 102.6us).
// ---------------------------------------------------------------------------
__global__ __launch_bounds__(256, 3) void kC_main(
    const float* __restrict__ v,   const float* __restrict__ H,
    const float* __restrict__ snr, const float* __restrict__ gd,
    const float* __restrict__ gc,  float* __restrict__ out)
{
    const int tid = threadIdx.x;
    const int gt  = blockIdx.x*256 + tid;
    const int k   = gt & 63;
    const long bl = gt >> 6;
    const int  b  = gt >> 16;
    const long g3 = (long)gt * 3;

    const float2* __restrict__ H2 = (const float2*)H;
    const long hbase = bl*(N_*K_) + k;

    // ---- h_power: stream H (order frozen: feeds channel logits) ----
    float hpv = 0.0f;
#pragma unroll
    for (int n = 0; n < N_; ++n) {
        float2 hv = __ldg(&H2[hbase + n*K_]);
        hpv = fmaf(hv.x, hv.x, fmaf(hv.y, hv.y, hpv));
    }

    const float2 vv   = ((const float2*)v)[gt];
    const float  snrv = snr[gt];
    const float  avgv = g_avg[(b<<6) | k];

    float pin[5] = { vv.x, vv.y, snrv, hpv, avgv };

    // ---- layer 1: 5 -> 32 (f32x2) ----
    ull acc[16];
    {
        const ull* bp = (const ull*)(cT + T_B1);
#pragma unroll
        for (int j = 0; j < 16; ++j) acc[j] = bp[j];
#pragma unroll
        for (int i = 0; i < 5; ++i) {
            ull xx = pack2(pin[i], pin[i]);
            const ulonglong2* wr = (const ulonglong2*)(cT + T_W1 + i*32);
#pragma unroll
            for (int j2 = 0; j2 < 8; ++j2) {
                ulonglong2 w = wr[j2];
                acc[j2*2+0] = ffma2(xx, w.x, acc[j2*2+0]);
                acc[j2*2+1] = ffma2(xx, w.y, acc[j2*2+1]);
            }
        }
    }
    float h1[32];
#pragma unroll
    for (int j = 0; j < 16; ++j) {
        float a, bq; unpack2(acc[j], a, bq);
        h1[2*j]   = fmaxf(a, 0.0f);
        h1[2*j+1] = fmaxf(bq, 0.0f);
    }

    // ---- gumbel loads issued here: hidden under layer-2 FMA ----
    const float gd0 = __ldg(&gd[g3+0]), gd1 = __ldg(&gd[g3+1]), gd2 = __ldg(&gd[g3+2]);
    const float gc0 = __ldg(&gc[g3+0]), gc1 = __ldg(&gc[g3+1]), gc2 = __ldg(&gc[g3+2]);

    // ---- layer 2: 32 -> 32 (f32x2), single pass, 8 independent chains ----
    {
        const ull* bp = (const ull*)(cT + T_B2);
#pragma unroll
        for (int j = 0; j < 16; ++j) acc[j] = bp[j];
#pragma unroll
        for (int i = 0; i < 32; ++i) {
            ull xx = pack2(h1[i], h1[i]);
            const ulonglong2* wr = (const ulonglong2*)(cT + T_W2 + i*32);
#pragma unroll
            for (int j2 = 0; j2 < 8; ++j2) {
                ulonglong2 w = wr[j2];
                acc[j2*2+0] = ffma2(xx, w.x, acc[j2*2+0]);
                acc[j2*2+1] = ffma2(xx, w.y, acc[j2*2+1]);
            }
        }
    }
    float h2[32];
#pragma unroll
    for (int j = 0; j < 16; ++j) {
        float a, bq; unpack2(acc[j], a, bq);
        h2[2*j]   = fmaxf(a, 0.0f);
        h2[2*j+1] = fmaxf(bq, 0.0f);
    }

    // ---- heads: packed (d0,d1)(d2,c0)(c1,c2) ----
    ull p0 = pack2(cT[T_BS+0], cT[T_BS+1]);
    ull p1 = pack2(cT[T_BS+2], cT[T_BS+3]);
    ull p2 = pack2(cT[T_BS+4], cT[T_BS+5]);
    {
#pragma unroll
        for (int i = 0; i < 32; ++i) {
            ull xx = pack2(h2[i], h2[i]);
            const ulonglong2* wa = (const ulonglong2*)(cT + T_WH + i*8);
            ulonglong2 w01 = wa[0];
            ull w2v = ((const ull*)(cT + T_WH + i*8))[2];
            p0 = ffma2(xx, w01.x, p0);
            p1 = ffma2(xx, w01.y, p1);
            p2 = ffma2(xx, w2v,   p2);
        }
    }
    float ld0, ld1, ld2, lc0, lc1, lc2;
    unpack2(p0, ld0, ld1);
    unpack2(p1, ld2, lc0);
    unpack2(p2, lc1, lc2);

    // ---- gumbel argmax ----
    float a0 = ld0 + gd0, a1 = ld1 + gd1, a2 = ld2 + gd2;
    int ad = 0; { float best = a0; if (a1 > best) { best = a1; ad = 1; } if (a2 > best) { ad = 2; } }
    float c0 = lc0 + gc0, c1 = lc1 + gc1, c2 = lc2 + gc2;
    int ac = 0; { float best = c0; if (c1 > best) { best = c1; ac = 1; } if (c2 > best) { ac = 2; } }

    // ---- quantizer parameter selection ----
    const bool  fd  = (ad != 0);
    const float sd  = (ad == 2) ? cT[T_BS+9]  : cT[T_BS+8];
    const float rsd = (ad == 2) ? cT[T_BS+13] : cT[T_BS+12];
    const float qnd = (ad == 2) ? -8.0f : -2.0f;
    const float qpd = (ad == 2) ?  7.0f :  1.0f;

    const bool  fc  = (ac != 0);
    const float sc  = (ac == 2) ? cT[T_BS+11] : cT[T_BS+10];
    const float rsc = (ac == 2) ? cT[T_BS+15] : cT[T_BS+14];
    const float qnc = (ac == 2) ? -8.0f : -2.0f;
    const float qpc = (ac == 2) ?  7.0f :  1.0f;

    // ---- cheap scalar outputs ----
    out[OFF_EBD + gt] = (ad == 1) ? 4.0f  : ((ad == 2) ? 8.0f  : 0.0f);
    out[OFF_EBC + gt] = (ac == 1) ? 32.0f : ((ac == 2) ? 64.0f : 0.0f);
    out[OFF_WD + g3+0] = (ad == 0) ? 1.0f : 0.0f;
    out[OFF_WD + g3+1] = (ad == 1) ? 1.0f : 0.0f;
    out[OFF_WD + g3+2] = (ad == 2) ? 1.0f : 0.0f;
    out[OFF_WC + g3+0] = (ac == 0) ? 1.0f : 0.0f;
    out[OFF_WC + g3+1] = (ac == 1) ? 1.0f : 0.0f;
    out[OFF_WC + g3+2] = (ac == 2) ? 1.0f : 0.0f;

    // ---- v_q (scalar lsq) ----
    {
        float2 vq;
        vq.x = fd ? lsqv(vv.x, rsd, sd, qnd, qpd) : 0.0f;
        vq.y = fd ? lsqv(vv.y, rsd, sd, qnd, qpd) : 0.0f;
        ((float2*)(out + OFF_VQ))[gt] = vq;
    }

    // ---- H_q: reload H (L2 hit), scalar lsq ----
    float2* __restrict__ HQ2 = (float2*)(out + OFF_HQ);
#pragma unroll
    for (int n = 0; n < N_; ++n) {
        float2 hv = __ldg(&H2[hbase + n*K_]);
        float2 hq;
        hq.x = fc ? lsqv(hv.x, rsc, sc, qnc, qpc) : 0.0f;
        hq.y = fc ? lsqv(hv.y, rsc, sc, qnc, qpc) : 0.0f;
        HQ2[hbase + n*K_] = hq;
    }
}

// ---------------------------------------------------------------------------
// Launch: fork/join so [kP -> memcpy] runs parallel with kA in the graph.
// ---------------------------------------------------------------------------
extern "C" void kernel_launch(void* const* d_in, const int* in_sizes, int n_in,
                              void* d_out, int out_size) {
    const float* v   = (const float*)d_in[0];
    const float* H   = (const float*)d_in[1];
    const float* snr = (const float*)d_in[2];
    const float* gd  = (const float*)d_in[3];
    const float* gc  = (const float*)d_in[4];
    const float* W1  = (const float*)d_in[5];
    const float* b1  = (const float*)d_in[6];
    const float* W2  = (const float*)d_in[7];
    const float* b2  = (const float*)d_in[8];
    const float* Wd  = (const float*)d_in[9];
    const float* bd  = (const float*)d_in[10];
    const float* Wc  = (const float*)d_in[11];
    const float* bc  = (const float*)d_in[12];
    const float* s2d = (const float*)d_in[13];
    const float* s4d = (const float*)d_in[14];
    const float* s2c = (const float*)d_in[15];
    const float* s4c = (const float*)d_in[16];
    float* out = (float*)d_out;

    void* p_stage = nullptr;
    cudaGetSymbolAddress(&p_stage, g_stage);

    cudaStream_t s2;
    cudaEvent_t evFork, evJoin;
    cudaStreamCreateWithFlags(&s2, cudaStreamNonBlocking);
    cudaEventCreateWithFlags(&evFork, cudaEventDisableTiming);
    cudaEventCreateWithFlags(&evJoin, cudaEventDisableTiming);

    // Fork s2 from the (possibly capturing) default stream
    cudaEventRecord(evFork, 0);
    cudaStreamWaitEvent(s2, evFork, 0);

    // Branch A (s2): stage tables -> constant bank
    kP_prep<<<1, 256, 0, s2>>>(W1, b1, W2, b2, Wd, Wc, bd, bc, s2d, s4d, s2c, s4c);
    cudaMemcpyToSymbolAsync(cT, p_stage, T_TOTAL*sizeof(float), 0,
                            cudaMemcpyDeviceToDevice, s2);
    cudaEventRecord(evJoin, s2);

    // Branch B (default stream): avg_power reduction
    kA_avg<<<NPART, 128>>>(H);

    // Join, then main kernel
    cudaStreamWaitEvent(0, evJoin, 0);
    kC_main<<<BLK_/256, 256>>>(v, H, snr, gd, gc, out);

    // Release handles (not device memory; graph retains captured structure)
    cudaEventDestroy(evFork);
    cudaEventDestroy(evJoin);
    cudaStreamDestroy(s2);
}

// round 14
// speedup vs baseline: 1.0556x; 1.0556x over previous
#include <cuda_runtime.h>

// Problem constants
#define B_   32
#define L_   1024
#define K_   64
#define N_   8
#define BLK_ (B_*L_*K_)          // 2,097,152 samples
#define CHUNK_L 32
#define CHUNKS  (L_/CHUNK_L)
#define NPART   (B_*CHUNKS)

// Output layout (flat f32, reference tuple order)
#define OFF_VQ  0L
#define OFF_HQ  4194304L
#define OFF_EBD 37748736L
#define OFF_EBC 39845888L
#define OFF_WD  41943040L
#define OFF_WC  48234496L

#define RND_MAGIC 12582912.0f    // 1.5 * 2^23 : exact RNE round for |x| <= 8

// Constant table layout (floats)
#define T_W1 0        // 160
#define T_W2 160      // 1024
#define T_B1 1184     // 32
#define T_B2 1216     // 32
#define T_WH 1248     // 256 (per i: d0 d1 d2 c0 c1 c2 0 0)
#define T_BS 1504     // 16  ([0..5]=bd,bc  [8..15]=s2d s4d s2c s4c r2d r4d r2c r4c)
#define T_TOTAL 1520

typedef unsigned long long ull;

// Scratch (device globals: allocation-free)
__device__ float    g_part[NPART*K_];
__device__ float    g_avg[B_*K_];
__device__ unsigned g_ctr;
__device__ __align__(16) float g_stage[T_TOTAL];

// One constant table (uniform-constant port, not L1)
__constant__ __align__(16) float cT[T_TOTAL];

// ---- packed f32x2 helpers (bitwise-exact dual fp32 ops) ----
__device__ __forceinline__ ull pack2(float x, float y) {
    ull r; asm("mov.b64 %0,{%1,%2};" : "=l"(r) : "f"(x), "f"(y)); return r;
}
__device__ __forceinline__ void unpack2(ull v, float& x, float& y) {
    asm("mov.b64 {%0,%1},%2;" : "=f"(x), "=f"(y) : "l"(v));
}
__device__ __forceinline__ ull ffma2(ull a, ull b, ull c) {
    ull d; asm("fma.rn.f32x2 %0,%1,%2,%3;" : "=l"(d) : "l"(a), "l"(b), "l"(c)); return d;
}

// ---------------------------------------------------------------------------
// Kernel A: avg_power via float4 loads with deep prefetch (8 loads staged per
// r-iteration; launch_bounds(128,4) lifts the 32-reg MLP ceiling seen in R6).
// Per-k fmaf chain and (P0+P1)+(P2+P3) tree are UNCHANGED -> g_avg
// bit-identical. Block 0 stages the constant table (single memcpy follows).
// ---------------------------------------------------------------------------
__global__ __launch_bounds__(128, 4) void kA_avg(
    const float* __restrict__ H,
    const float* __restrict__ W1, const float* __restrict__ b1,
    const float* __restrict__ W2, const float* __restrict__ b2,
    const float* __restrict__ Wd, const float* __restrict__ Wc,
    const float* __restrict__ bd, const float* __restrict__ bc,
    const float* __restrict__ s2d, const float* __restrict__ s4d,
    const float* __restrict__ s2c, const float* __restrict__ s4c)
{
    const int bx  = blockIdx.x;
    const int tid = threadIdx.x;

    if (bx == 0) {
        for (int i = tid; i < 160;  i += 128) g_stage[T_W1 + i] = W1[i];
        for (int i = tid; i < 1024; i += 128) g_stage[T_W2 + i] = W2[i];
        if (tid < 32) {
            g_stage[T_B1 + tid] = b1[tid];
            g_stage[T_B2 + tid] = b2[tid];
            g_stage[T_WH + tid*8+0] = Wd[tid*3+0];
            g_stage[T_WH + tid*8+1] = Wd[tid*3+1];
            g_stage[T_WH + tid*8+2] = Wd[tid*3+2];
            g_stage[T_WH + tid*8+3] = Wc[tid*3+0];
            g_stage[T_WH + tid*8+4] = Wc[tid*3+1];
            g_stage[T_WH + tid*8+5] = Wc[tid*3+2];
            g_stage[T_WH + tid*8+6] = 0.0f;
            g_stage[T_WH + tid*8+7] = 0.0f;
        }
        if (tid == 0) {
            g_stage[T_BS+0] = bd[0]; g_stage[T_BS+1] = bd[1]; g_stage[T_BS+2] = bd[2];
            g_stage[T_BS+3] = bc[0]; g_stage[T_BS+4] = bc[1]; g_stage[T_BS+5] = bc[2];
            g_stage[T_BS+6] = 0.0f;  g_stage[T_BS+7] = 0.0f;
            float a = *s2d, bq = *s4d, c = *s2c, d = *s4c;
            g_stage[T_BS+8]  = a;      g_stage[T_BS+9]  = bq;
            g_stage[T_BS+10] = c;      g_stage[T_BS+11] = d;
            g_stage[T_BS+12] = 1.0f/a; g_stage[T_BS+13] = 1.0f/bq;
            g_stage[T_BS+14] = 1.0f/c; g_stage[T_BS+15] = 1.0f/d;
        }
    }

    const int b     = bx >> 5;
    const int chunk = bx & 31;
    const int k2    = tid & 31;
    const int lsub  = tid >> 5;

    const float4* __restrict__ H4 = (const float4*)H;

    float pA = 0.0f, pB = 0.0f;
#pragma unroll
    for (int r = 0; r < CHUNK_L/4; ++r) {
        const int l  = chunk*CHUNK_L + r*4 + lsub;
        const long bl = (long)b*L_ + l;
        // stage all 8 loads first: deep MLP
        float4 hv[N_];
#pragma unroll
        for (int n = 0; n < N_; ++n)
            hv[n] = H4[(bl*N_ + n)*(K_/2) + k2];
        // fma chain: identical order to all prior rounds
        float hpA = 0.0f, hpB = 0.0f;
#pragma unroll
        for (int n = 0; n < N_; ++n) {
            hpA = fmaf(hv[n].x, hv[n].x, fmaf(hv[n].y, hv[n].y, hpA));
            hpB = fmaf(hv[n].z, hv[n].z, fmaf(hv[n].w, hv[n].w, hpB));
        }
        pA += hpA;
        pB += hpB;
    }

    __shared__ float2 sm[128];
    __shared__ unsigned s_ticket;
    sm[tid] = make_float2(pA, pB);
    __syncthreads();
    if (tid < 32) {
        float2 q0 = sm[tid], q1 = sm[tid+32], q2 = sm[tid+64], q3 = sm[tid+96];
        float sA = (q0.x + q1.x) + (q2.x + q3.x);
        float sB = (q0.y + q1.y) + (q2.y + q3.y);
        g_part[bx*64 + 2*tid + 0] = sA;
        g_part[bx*64 + 2*tid + 1] = sB;
    }
    __threadfence();
    __syncthreads();
    if (tid == 0) s_ticket = atomicAdd(&g_ctr, 1u);
    __syncthreads();

    if (s_ticket == NPART - 1) {
        for (int i = tid; i < B_*K_; i += 128) {
            const int bb = i >> 6;
            const int kk = i & 63;
            float s = 0.0f;
#pragma unroll
            for (int c = 0; c < CHUNKS; ++c)
                s += g_part[(bb*CHUNKS + c)*64 + kk];
            g_avg[i] = s * (1.0f/1024.0f);
        }
        if (tid == 0) g_ctr = 0;
    }
}

// ---------------------------------------------------------------------------
// lsq forward (scalar): round(clip(x*rs, Qn, Qp)) * s, exact RNE via magic.
// ---------------------------------------------------------------------------
__device__ __forceinline__ float lsqv(float x, float rs, float s, float qn, float qp) {
    float t = x * rs;
    t = fminf(fmaxf(t, qn), qp);
    t = __fadd_rn(__fadd_rn(t, RND_MAGIC), -RND_MAGIC);
    return t * s;
}

// ---------------------------------------------------------------------------
// Kernel C: R11 configuration verbatim (best measured: 102.6us).
// ---------------------------------------------------------------------------
__global__ __launch_bounds__(256, 3) void kC_main(
    const float* __restrict__ v,   const float* __restrict__ H,
    const float* __restrict__ snr, const float* __restrict__ gd,
    const float* __restrict__ gc,  float* __restrict__ out)
{
    const int tid = threadIdx.x;
    const int gt  = blockIdx.x*256 + tid;
    const int k   = gt & 63;
    const long bl = gt >> 6;
    const int  b  = gt >> 16;
    const long g3 = (long)gt * 3;

    const float2* __restrict__ H2 = (const float2*)H;
    const long hbase = bl*(N_*K_) + k;

    // ---- h_power: stream H (order frozen: feeds channel logits) ----
    float hpv = 0.0f;
#pragma unroll
    for (int n = 0; n < N_; ++n) {
        float2 hv = __ldg(&H2[hbase + n*K_]);
        hpv = fmaf(hv.x, hv.x, fmaf(hv.y, hv.y, hpv));
    }

    const float2 vv   = ((const float2*)v)[gt];
    const float  snrv = snr[gt];
    const float  avgv = g_avg[(b<<6) | k];

    float pin[5] = { vv.x, vv.y, snrv, hpv, avgv };

    // ---- layer 1: 5 -> 32 (f32x2) ----
    ull acc[16];
    {
        const ull* bp = (const ull*)(cT + T_B1);
#pragma unroll
        for (int j = 0; j < 16; ++j) acc[j] = bp[j];
#pragma unroll
        for (int i = 0; i < 5; ++i) {
            ull xx = pack2(pin[i], pin[i]);
            const ulonglong2* wr = (const ulonglong2*)(cT + T_W1 + i*32);
#pragma unroll
            for (int j2 = 0; j2 < 8; ++j2) {
                ulonglong2 w = wr[j2];
                acc[j2*2+0] = ffma2(xx, w.x, acc[j2*2+0]);
                acc[j2*2+1] = ffma2(xx, w.y, acc[j2*2+1]);
            }
        }
    }
    float h1[32];
#pragma unroll
    for (int j = 0; j < 16; ++j) {
        float a, bq; unpack2(acc[j], a, bq);
        h1[2*j]   = fmaxf(a, 0.0f);
        h1[2*j+1] = fmaxf(bq, 0.0f);
    }

    // ---- gumbel loads issued here: hidden under layer-2 FMA ----
    const float gd0 = __ldg(&gd[g3+0]), gd1 = __ldg(&gd[g3+1]), gd2 = __ldg(&gd[g3+2]);
    const float gc0 = __ldg(&gc[g3+0]), gc1 = __ldg(&gc[g3+1]), gc2 = __ldg(&gc[g3+2]);

    // ---- layer 2: 32 -> 32 (f32x2), single pass, 8 independent chains ----
    {
        const ull* bp = (const ull*)(cT + T_B2);
#pragma unroll
        for (int j = 0; j < 16; ++j) acc[j] = bp[j];
#pragma unroll
        for (int i = 0; i < 32; ++i) {
            ull xx = pack2(h1[i], h1[i]);
            const ulonglong2* wr = (const ulonglong2*)(cT + T_W2 + i*32);
#pragma unroll
            for (int j2 = 0; j2 < 8; ++j2) {
                ulonglong2 w = wr[j2];
                acc[j2*2+0] = ffma2(xx, w.x, acc[j2*2+0]);
                acc[j2*2+1] = ffma2(xx, w.y, acc[j2*2+1]);
            }
        }
    }
    float h2[32];
#pragma unroll
    for (int j = 0; j < 16; ++j) {
        float a, bq; unpack2(acc[j], a, bq);
        h2[2*j]   = fmaxf(a, 0.0f);
        h2[2*j+1] = fmaxf(bq, 0.0f);
    }

    // ---- heads: packed (d0,d1)(d2,c0)(c1,c2) ----
    ull p0 = pack2(cT[T_BS+0], cT[T_BS+1]);
    ull p1 = pack2(cT[T_BS+2], cT[T_BS+3]);
    ull p2 = pack2(cT[T_BS+4], cT[T_BS+5]);
    {
#pragma unroll
        for (int i = 0; i < 32; ++i) {
            ull xx = pack2(h2[i], h2[i]);
            const ulonglong2* wa = (const ulonglong2*)(cT + T_WH + i*8);
            ulonglong2 w01 = wa[0];
            ull w2v = ((const ull*)(cT + T_WH + i*8))[2];
            p0 = ffma2(xx, w01.x, p0);
            p1 = ffma2(xx, w01.y, p1);
            p2 = ffma2(xx, w2v,   p2);
        }
    }
    float ld0, ld1, ld2, lc0, lc1, lc2;
    unpack2(p0, ld0, ld1);
    unpack2(p1, ld2, lc0);
    unpack2(p2, lc1, lc2);

    // ---- gumbel argmax ----
    float a0 = ld0 + gd0, a1 = ld1 + gd1, a2 = ld2 + gd2;
    int ad = 0; { float best = a0; if (a1 > best) { best = a1; ad = 1; } if (a2 > best) { ad = 2; } }
    float c0 = lc0 + gc0, c1 = lc1 + gc1, c2 = lc2 + gc2;
    int ac = 0; { float best = c0; if (c1 > best) { best = c1; ac = 1; } if (c2 > best) { ac = 2; } }

    // ---- quantizer parameter selection ----
    const bool  fd  = (ad != 0);
    const float sd  = (ad == 2) ? cT[T_BS+9]  : cT[T_BS+8];
    const float rsd = (ad == 2) ? cT[T_BS+13] : cT[T_BS+12];
    const float qnd = (ad == 2) ? -8.0f : -2.0f;
    const float qpd = (ad == 2) ?  7.0f :  1.0f;

    const bool  fc  = (ac != 0);
    const float sc  = (ac == 2) ? cT[T_BS+11] : cT[T_BS+10];
    const float rsc = (ac == 2) ? cT[T_BS+15] : cT[T_BS+14];
    const float qnc = (ac == 2) ? -8.0f : -2.0f;
    const float qpc = (ac == 2) ?  7.0f :  1.0f;

    // ---- cheap scalar outputs ----
    out[OFF_EBD + gt] = (ad == 1) ? 4.0f  : ((ad == 2) ? 8.0f  : 0.0f);
    out[OFF_EBC + gt] = (ac == 1) ? 32.0f : ((ac == 2) ? 64.0f : 0.0f);
    out[OFF_WD + g3+0] = (ad == 0) ? 1.0f : 0.0f;
    out[OFF_WD + g3+1] = (ad == 1) ? 1.0f : 0.0f;
    out[OFF_WD + g3+2] = (ad == 2) ? 1.0f : 0.0f;
    out[OFF_WC + g3+0] = (ac == 0) ? 1.0f : 0.0f;
    out[OFF_WC + g3+1] = (ac == 1) ? 1.0f : 0.0f;
    out[OFF_WC + g3+2] = (ac == 2) ? 1.0f : 0.0f;

    // ---- v_q (scalar lsq) ----
    {
        float2 vq;
        vq.x = fd ? lsqv(vv.x, rsd, sd, qnd, qpd) : 0.0f;
        vq.y = fd ? lsqv(vv.y, rsd, sd, qnd, qpd) : 0.0f;
        ((float2*)(out + OFF_VQ))[gt] = vq;
    }

    // ---- H_q: reload H (L2 hit), scalar lsq ----
    float2* __restrict__ HQ2 = (float2*)(out + OFF_HQ);
#pragma unroll
    for (int n = 0; n < N_; ++n) {
        float2 hv = __ldg(&H2[hbase + n*K_]);
        float2 hq;
        hq.x = fc ? lsqv(hv.x, rsc, sc, qnc, qpc) : 0.0f;
        hq.y = fc ? lsqv(hv.y, rsc, sc, qnc, qpc) : 0.0f;
        HQ2[hbase + n*K_] = hq;
    }
}

// ---------------------------------------------------------------------------
// Launch (R11 topology: kA w/ staging -> single memcpy -> kC)
// ---------------------------------------------------------------------------
extern "C" void kernel_launch(void* const* d_in, const int* in_sizes, int n_in,
                              void* d_out, int out_size) {
    const float* v   = (const float*)d_in[0];
    const float* H   = (const float*)d_in[1];
    const float* snr = (const float*)d_in[2];
    const float* gd  = (const float*)d_in[3];
    const float* gc  = (const float*)d_in[4];
    const float* W1  = (const float*)d_in[5];
    const float* b1  = (const float*)d_in[6];
    const float* W2  = (const float*)d_in[7];
    const float* b2  = (const float*)d_in[8];
    const float* Wd  = (const float*)d_in[9];
    const float* bd  = (const float*)d_in[10];
    const float* Wc  = (const float*)d_in[11];
    const float* bc  = (const float*)d_in[12];
    const float* s2d = (const float*)d_in[13];
    const float* s4d = (const float*)d_in[14];
    const float* s2c = (const float*)d_in[15];
    const float* s4c = (const float*)d_in[16];
    float* out = (float*)d_out;

    kA_avg<<<NPART, 128>>>(H, W1, b1, W2, b2, Wd, Wc, bd, bc, s2d, s4d, s2c, s4c);

    void* p_stage = nullptr;
    cudaGetSymbolAddress(&p_stage, g_stage);
    cudaMemcpyToSymbolAsync(cT, p_stage, T_TOTAL*sizeof(float), 0,
                            cudaMemcpyDeviceToDevice, 0);

    kC_main<<<BLK_/256, 256>>>(v, H, snr, gd, gc, out);
}